// round 3
// baseline (speedup 1.0000x reference)
#include <cuda_runtime.h>
#include <cuda_bf16.h>

#define EPS 1e-6f
#define NB 16
#define NA 10
#define NT 30
#define NP_POLY 16
#define NV 200
#define SEG_PER_POLY (NV - 1)            // 199
#define NPTS_WARP 8
#define WARPS 4
#define THREADS (WARPS * 32)             // 128
#define PTSLOTS (WARPS * NPTS_WARP)      // 32 >= NT
#define NBA (NB * NA)                    // 160
#define GRID (NBA * NP_POLY)             // 2560

// partial results: [ba][t(32)][poly(16)]  (poly contiguous -> float4/int4 loads)
__device__ float g_md[NBA * PTSLOTS * NP_POLY];
__device__ int   g_ct[NBA * PTSLOTS * NP_POLY];
__device__ unsigned g_counter = 0;

__global__ __launch_bounds__(THREADS)
void offroad_fused_kernel(const float* __restrict__ points,
                          const float* __restrict__ polys,
                          float* __restrict__ out) {
    __shared__ float4 s4[SEG_PER_POLY];   // {sx, sy, ex, ey}
    __shared__ float2 s2[SEG_PER_POLY];   // {1/(esq+eps), 1/(slope+eps)}
    __shared__ int s_isLast;

    int bx = blockIdx.x;
    int p  = bx & (NP_POLY - 1);
    int ba = bx >> 4;                     // b*NA + a
    int b  = ba / NA;

    // ---- in-block segment precompute (exact IEEE divisions, matches ref) ----
    const float2* pv = (const float2*)polys + ((size_t)(b * NP_POLY + p)) * NV;
    for (int i = threadIdx.x; i < SEG_PER_POLY; i += THREADS) {
        float2 v0 = pv[i];
        float2 v1 = pv[i + 1];
        float evx = v1.x - v0.x;
        float evy = v1.y - v0.y;
        float esq = fmaf(evx, evx, evy * evy);
        float rcp_esq = 1.0f / (esq + EPS);
        float slope   = evy / (evx + EPS);
        float rcp_sl  = 1.0f / (slope + EPS);
        s4[i] = make_float4(v0.x, v0.y, v1.x, v1.y);
        s2[i] = make_float2(rcp_esq, rcp_sl);
    }
    __syncthreads();

    // ---- sweep ----
    int wid = threadIdx.x >> 5;
    int ln  = threadIdx.x & 31;
    int t0  = wid * NPTS_WARP;

    float px[NPTS_WARP], py[NPTS_WARP], md[NPTS_WARP];
    int   ct[NPTS_WARP];

    const float2* pts2 = (const float2*)points;
#pragma unroll
    for (int k = 0; k < NPTS_WARP; k++) {
        int t = t0 + k;
        float2 pt = (t < NT) ? pts2[ba * NT + t] : make_float2(1e30f, 1e30f);
        px[k] = pt.x; py[k] = pt.y;
        md[k] = 3.4e38f;
        ct[k] = 0;
    }

    for (int s = ln; s < SEG_PER_POLY; s += 32) {
        float4 sg = s4[s];
        float2 rr = s2[s];
        float evx = sg.z - sg.x;
        float evy = sg.w - sg.y;
#pragma unroll
        for (int k = 0; k < NPTS_WARP; k++) {
            float v1x = px[k] - sg.x;
            float v1y = py[k] - sg.y;
            float dot = fmaf(v1x, evx, v1y * evy);
            float proj = __saturatef(dot * rr.x);
            float dx = fmaf(-evx, proj, v1x);
            float dy = fmaf(-evy, proj, v1y);
            float d2 = fmaf(dx, dx, dy * dy);
            md[k] = fminf(md[k], d2);
            bool c1 = (sg.y <= py[k]);
            bool c2 = (sg.w <= py[k]);
            float ix = fmaf(v1y, rr.y, sg.x);
            ct[k] += ((c1 != c2) & (ix > px[k])) ? 1 : 0;
        }
    }

    // ---- warp reduction ----
#pragma unroll
    for (int k = 0; k < NPTS_WARP; k++) {
#pragma unroll
        for (int o = 16; o > 0; o >>= 1) {
            md[k] = fminf(md[k], __shfl_xor_sync(0xffffffffu, md[k], o));
            ct[k] += __shfl_xor_sync(0xffffffffu, ct[k], o);
        }
    }

    if (ln == 0) {
#pragma unroll
        for (int k = 0; k < NPTS_WARP; k++) {
            int t = t0 + k;
            int idx = (ba * PTSLOTS + t) * NP_POLY + p;
            g_md[idx] = md[k];
            g_ct[idx] = ct[k];
        }
        __threadfence();   // make partials globally visible before counting in
    }
    __syncthreads();

    // ---- last-block final reduce ----
    if (threadIdx.x == 0) {
        unsigned old = atomicAdd(&g_counter, 1u);
        s_isLast = (old == (unsigned)(GRID - 1));
        if (s_isLast) g_counter = 0;   // self-reset for next graph replay
    }
    __syncthreads();

    if (s_isLast) {
        __threadfence();
        for (int o = threadIdx.x; o < NBA; o += THREADS) {
            float sum = 0.0f;
#pragma unroll 2
            for (int t = 0; t < NT; t++) {
                const float4* pm = (const float4*)(g_md + (o * PTSLOTS + t) * NP_POLY);
                const int4*   pc = (const int4*)  (g_ct + (o * PTSLOTS + t) * NP_POLY);
                float m = 3.4e38f;
                int   c = 0;
#pragma unroll
                for (int q = 0; q < NP_POLY / 4; q++) {
                    float4 mv = pm[q];
                    int4   cv = pc[q];
                    m = fminf(m, fminf(fminf(mv.x, mv.y), fminf(mv.z, mv.w)));
                    c += cv.x + cv.y + cv.z + cv.w;
                }
                float d = sqrtf(fmaxf(m, EPS));
                if (c & 1) d = -d;
                sum += fmaxf(d + 0.5f, 0.0f);
            }
            out[o] = sum;
        }
    }
}

extern "C" void kernel_launch(void* const* d_in, const int* in_sizes, int n_in,
                              void* d_out, int out_size) {
    const float* points = (const float*)d_in[0];  // (16,10,30,2)
    const float* polys  = (const float*)d_in[1];  // (16,16,200,2)
    float* out = (float*)d_out;                   // (16,10)

    offroad_fused_kernel<<<GRID, THREADS>>>(points, polys, out);
}

// round 4
// speedup vs baseline: 2.0741x; 2.0741x over previous
#include <cuda_runtime.h>
#include <cuda_bf16.h>

#define EPS 1e-6f
#define NB 16
#define NA 10
#define NT 30
#define NP_POLY 16
#define NV 200
#define SEGP (NV - 1)               // 199 segments per polygon
#define NPTS 300                    // points per batch (NA*NT)
#define NPTS_WARP 8
#define WARPS 8
#define THREADS (WARPS * 32)        // 256
#define PASSES 5                    // 5*64 = 320 >= 300
#define NBA (NB * NA)               // 160

// partials: [b*300 + pidx][poly]
__device__ float g_md[NB * NPTS * NP_POLY];
__device__ int   g_ct[NB * NPTS * NP_POLY];

__global__ __launch_bounds__(THREADS, 2)
void offroad_main_kernel(const float* __restrict__ points,
                         const float* __restrict__ polys) {
    __shared__ float4 s4[SEGP];   // {sx, sy, ex, ey}
    __shared__ float2 s2[SEGP];   // {1/(esq+eps), 1/(slope+eps)}

    int b = blockIdx.x >> 4;
    int p = blockIdx.x & (NP_POLY - 1);

    // ---- per-block segment precompute: ONE div-chain per thread ----
    int tid = threadIdx.x;
    if (tid < SEGP) {
        const float2* pv = (const float2*)polys + ((size_t)(b * NP_POLY + p)) * NV;
        float2 v0 = pv[tid];
        float2 v1 = pv[tid + 1];
        float evx = v1.x - v0.x;
        float evy = v1.y - v0.y;
        float esq = fmaf(evx, evx, evy * evy);
        float rcp_esq = 1.0f / (esq + EPS);          // exact IEEE
        float slope   = evy / (evx + EPS);           // exact IEEE
        float rcp_sl  = 1.0f / (slope + EPS);        // exact IEEE
        s4[tid] = make_float4(v0.x, v0.y, v1.x, v1.y);
        s2[tid] = make_float2(rcp_esq, rcp_sl);
    }
    __syncthreads();

    int wid = tid >> 5;
    int ln  = tid & 31;
    const float2* pts2 = (const float2*)points + (size_t)b * NPTS;

#pragma unroll 1
    for (int pass = 0; pass < PASSES; pass++) {
        int pbase = pass * (WARPS * NPTS_WARP) + wid * NPTS_WARP;
        if (pbase >= NPTS) continue;   // whole warp has no valid points

        float px[NPTS_WARP], py[NPTS_WARP], md[NPTS_WARP];
        int   ct[NPTS_WARP];
#pragma unroll
        for (int k = 0; k < NPTS_WARP; k++) {
            int pidx = pbase + k;
            float2 pt = (pidx < NPTS) ? pts2[pidx] : make_float2(1e30f, 1e30f);
            px[k] = pt.x; py[k] = pt.y;
            md[k] = 3.4e38f;
            ct[k] = 0;
        }

        // lanes stride over segments
        for (int s = ln; s < SEGP; s += 32) {
            float4 sg = s4[s];
            float2 rr = s2[s];
            float evx = sg.z - sg.x;
            float evy = sg.w - sg.y;
#pragma unroll
            for (int k = 0; k < NPTS_WARP; k++) {
                float v1x = px[k] - sg.x;
                float v1y = py[k] - sg.y;
                float dot = fmaf(v1x, evx, v1y * evy);
                float proj = __saturatef(dot * rr.x);
                float dx = fmaf(-evx, proj, v1x);
                float dy = fmaf(-evy, proj, v1y);
                float d2 = fmaf(dx, dx, dy * dy);
                md[k] = fminf(md[k], d2);
                bool c1 = (sg.y <= py[k]);
                bool c2 = (sg.w <= py[k]);
                float ix = fmaf(v1y, rr.y, sg.x);
                ct[k] += ((c1 != c2) & (ix > px[k])) ? 1 : 0;
            }
        }

        // warp reduction
#pragma unroll
        for (int k = 0; k < NPTS_WARP; k++) {
#pragma unroll
            for (int o = 16; o > 0; o >>= 1) {
                md[k] = fminf(md[k], __shfl_xor_sync(0xffffffffu, md[k], o));
                ct[k] += __shfl_xor_sync(0xffffffffu, ct[k], o);
            }
        }

        if (ln == 0) {
#pragma unroll
            for (int k = 0; k < NPTS_WARP; k++) {
                int pidx = pbase + k;
                if (pidx < NPTS) {
                    int idx = (b * NPTS + pidx) * NP_POLY + p;
                    g_md[idx] = md[k];
                    g_ct[idx] = ct[k];
                }
            }
        }
    }
}

__global__ __launch_bounds__(THREADS)
void reduce_kernel(float* __restrict__ out) {
    __shared__ float s_sum[WARPS];
    int ba = blockIdx.x;                 // 0..159  = b*NA + a
    int wid = threadIdx.x >> 5;
    int ln  = threadIdx.x & 31;

    float wsum = 0.0f;
    // warp w handles t = w, w+8, w+16, w+24  (fixed ascending order)
    for (int t = wid; t < NT; t += WARPS) {
        int base = (ba * NT + t) * NP_POLY;   // ba*NT = b*300 + a*30 -> matches main layout
        float md = 3.4e38f;
        int   ct = 0;
        if (ln < NP_POLY) {
            md = g_md[base + ln];
            ct = g_ct[base + ln];
        }
#pragma unroll
        for (int o = 16; o > 0; o >>= 1) {
            md = fminf(md, __shfl_xor_sync(0xffffffffu, md, o));
            ct += __shfl_xor_sync(0xffffffffu, ct, o);
        }
        float d = sqrtf(fmaxf(md, EPS));
        if (ct & 1) d = -d;
        wsum += fmaxf(d + 0.5f, 0.0f);
    }
    if (ln == 0) s_sum[wid] = wsum;
    __syncthreads();
    if (threadIdx.x == 0) {
        float sum = 0.0f;
#pragma unroll
        for (int w = 0; w < WARPS; w++) sum += s_sum[w];
        out[ba] = sum;
    }
}

extern "C" void kernel_launch(void* const* d_in, const int* in_sizes, int n_in,
                              void* d_out, int out_size) {
    const float* points = (const float*)d_in[0];  // (16,10,30,2)
    const float* polys  = (const float*)d_in[1];  // (16,16,200,2)
    float* out = (float*)d_out;                   // (16,10)

    offroad_main_kernel<<<NB * NP_POLY, THREADS>>>(points, polys);
    reduce_kernel<<<NBA, THREADS>>>(out);
}